// round 1
// baseline (speedup 1.0000x reference)
#include <cuda_runtime.h>
#include <math.h>

#define M_TOTAL 8192
#define N_TOTAL 2048
#define K_TOTAL 2048
#define EPS 1e-5f

#define BM 128
#define BN 128
#define BK 8
#define TM 8
#define TN 8

__device__ float g_xsq[M_TOTAL];
__device__ float g_wsq[N_TOTAL];

// -------------------- row sum of squares: x_sq[m] = sum_k x[m][k]^2 --------------------
__global__ void row_sumsq_kernel(const float* __restrict__ x) {
    const int row = blockIdx.x;
    const float4* p = reinterpret_cast<const float4*>(x + (size_t)row * K_TOTAL);
    float sum = 0.f;
#pragma unroll
    for (int j = 0; j < 2; j++) {   // 512 float4 per row / 256 threads
        float4 v = p[threadIdx.x + j * 256];
        sum += v.x * v.x + v.y * v.y + v.z * v.z + v.w * v.w;
    }
#pragma unroll
    for (int off = 16; off > 0; off >>= 1)
        sum += __shfl_xor_sync(0xffffffffu, sum, off);
    __shared__ float s[8];
    if ((threadIdx.x & 31) == 0) s[threadIdx.x >> 5] = sum;
    __syncthreads();
    if (threadIdx.x < 8) {
        float v = s[threadIdx.x];
#pragma unroll
        for (int off = 4; off > 0; off >>= 1)
            v += __shfl_xor_sync(0xffu, v, off);
        if (threadIdx.x == 0) g_xsq[row] = v;
    }
}

// -------------------- column sum of squares: w_sq[n] = sum_k W[k][n]^2 --------------------
__global__ void zero_wsq_kernel() {
    int i = blockIdx.x * blockDim.x + threadIdx.x;
    if (i < N_TOTAL) g_wsq[i] = 0.f;
}

__global__ void col_sumsq_kernel(const float* __restrict__ w) {
    const int col = blockIdx.x * 128 + threadIdx.x;
    const int k0 = blockIdx.y * 256;
    float sum = 0.f;
#pragma unroll 8
    for (int k = 0; k < 256; k++) {
        float v = w[(size_t)(k0 + k) * N_TOTAL + col];
        sum += v * v;
    }
    atomicAdd(&g_wsq[col], sum);
}

// -------------------- fused GEMM + Yat epilogue --------------------
__global__ __launch_bounds__(256, 2)
void yat_gemm_kernel(const float* __restrict__ A,   // x  [M, K]
                     const float* __restrict__ B,   // W  [K, N]
                     const float* __restrict__ bias,
                     const float* __restrict__ alpha,
                     float* __restrict__ C) {
    __shared__ float As[2][BK][BM];
    __shared__ float Bs[2][BK][BN];

    const int tid = threadIdx.x;
    const int tx = tid & 15;       // 0..15 -> column group
    const int ty = tid >> 4;       // 0..15 -> row group
    const int row0 = blockIdx.y * BM;
    const int col0 = blockIdx.x * BN;

    // A-tile load mapping: 128 rows x 8 cols = 1024 floats = 256 x float4
    const int arow = tid >> 1;          // 0..127
    const int acol = (tid & 1) * 4;     // 0 or 4
    // B-tile load mapping: 8 rows x 128 cols
    const int brow = tid >> 5;          // 0..7
    const int bcol = (tid & 31) * 4;    // 0..124

    const float* Aptr = A + (size_t)(row0 + arow) * K_TOTAL + acol;
    const float* Bptr = B + (size_t)brow * N_TOTAL + col0 + bcol;

    float acc[TM][TN];
#pragma unroll
    for (int i = 0; i < TM; i++)
#pragma unroll
        for (int j = 0; j < TN; j++) acc[i][j] = 0.f;

    // prologue: load k-tile 0 into buffer 0
    {
        float4 va = *reinterpret_cast<const float4*>(Aptr);
        float4 vb = *reinterpret_cast<const float4*>(Bptr);
        As[0][acol + 0][arow] = va.x;
        As[0][acol + 1][arow] = va.y;
        As[0][acol + 2][arow] = va.z;
        As[0][acol + 3][arow] = va.w;
        *reinterpret_cast<float4*>(&Bs[0][brow][bcol]) = vb;
    }
    __syncthreads();

    const int NKT = K_TOTAL / BK;  // 256
    int buf = 0;
#pragma unroll 1
    for (int kt = 0; kt < NKT; kt++) {
        float4 va, vb;
        const bool has_next = (kt + 1 < NKT);
        if (has_next) {
            va = *reinterpret_cast<const float4*>(Aptr + (kt + 1) * BK);
            vb = *reinterpret_cast<const float4*>(Bptr + (size_t)(kt + 1) * BK * N_TOTAL);
        }

#pragma unroll
        for (int kk = 0; kk < BK; kk++) {
            float a[TM], b[TN];
            float4 a0 = *reinterpret_cast<const float4*>(&As[buf][kk][ty * TM]);
            float4 a1 = *reinterpret_cast<const float4*>(&As[buf][kk][ty * TM + 4]);
            float4 b0 = *reinterpret_cast<const float4*>(&Bs[buf][kk][tx * TN]);
            float4 b1 = *reinterpret_cast<const float4*>(&Bs[buf][kk][tx * TN + 4]);
            a[0] = a0.x; a[1] = a0.y; a[2] = a0.z; a[3] = a0.w;
            a[4] = a1.x; a[5] = a1.y; a[6] = a1.z; a[7] = a1.w;
            b[0] = b0.x; b[1] = b0.y; b[2] = b0.z; b[3] = b0.w;
            b[4] = b1.x; b[5] = b1.y; b[6] = b1.z; b[7] = b1.w;
#pragma unroll
            for (int i = 0; i < TM; i++)
#pragma unroll
                for (int j = 0; j < TN; j++)
                    acc[i][j] = fmaf(a[i], b[j], acc[i][j]);
        }

        if (has_next) {
            int nb = buf ^ 1;
            As[nb][acol + 0][arow] = va.x;
            As[nb][acol + 1][arow] = va.y;
            As[nb][acol + 2][arow] = va.z;
            As[nb][acol + 3][arow] = va.w;
            *reinterpret_cast<float4*>(&Bs[nb][brow][bcol]) = vb;
        }
        __syncthreads();
        buf ^= 1;
    }

    // -------------------- epilogue --------------------
    float xs[TM], ws[TN], bs[TN];
#pragma unroll
    for (int i = 0; i < TM; i++) xs[i] = g_xsq[row0 + ty * TM + i];
#pragma unroll
    for (int j = 0; j < TN; j++) {
        ws[j] = g_wsq[col0 + tx * TN + j];
        bs[j] = bias[col0 + tx * TN + j];
    }
    const float a_exp = __ldg(alpha);
    const float base = sqrtf(2048.0f) / logf(2049.0f);
    const float scale = powf(base, a_exp);

#pragma unroll
    for (int i = 0; i < TM; i++) {
        float vals[TN];
#pragma unroll
        for (int j = 0; j < TN; j++) {
            float y0 = acc[i][j];
            float d = xs[i] + ws[j] - 2.0f * y0 + EPS;
            float y = (y0 * y0) / d;
            vals[j] = (y + bs[j]) * scale;
        }
        float* outp = C + (size_t)(row0 + ty * TM + i) * N_TOTAL + col0 + tx * TN;
        float4 o0 = make_float4(vals[0], vals[1], vals[2], vals[3]);
        float4 o1 = make_float4(vals[4], vals[5], vals[6], vals[7]);
        *reinterpret_cast<float4*>(outp)     = o0;
        *reinterpret_cast<float4*>(outp + 4) = o1;
    }
}

// -------------------- launch --------------------
extern "C" void kernel_launch(void* const* d_in, const int* in_sizes, int n_in,
                              void* d_out, int out_size) {
    const float* x     = (const float*)d_in[0];  // [4,2048,2048] -> [8192,2048]
    const float* w     = (const float*)d_in[1];  // [2048,2048]
    const float* bias  = (const float*)d_in[2];  // [2048]
    const float* alpha = (const float*)d_in[3];  // [1]
    float* out = (float*)d_out;                  // [8192,2048]

    row_sumsq_kernel<<<M_TOTAL, 256>>>(x);
    zero_wsq_kernel<<<(N_TOTAL + 255) / 256, 256>>>();
    col_sumsq_kernel<<<dim3(N_TOTAL / 128, K_TOTAL / 256), 128>>>(w);
    yat_gemm_kernel<<<dim3(N_TOTAL / BN, M_TOTAL / BM), 256>>>(x, w, bias, alpha, out);
}

// round 3
// speedup vs baseline: 2.2438x; 2.2438x over previous
#include <cuda_runtime.h>
#include <cuda_bf16.h>
#include <cstdint>
#include <math.h>

#define M_TOTAL 8192
#define N_TOTAL 2048
#define K_TOTAL 2048
#define EPS 1e-5f

#define BM 128
#define BN 128
#define BK 32
#define NSTAGE 4
#define SROW 80                        // bytes per smem tile row (32 bf16 + 8 pad)
#define TILE_BYTES (128 * SROW)        // 10240
#define STAGE_BYTES (2 * TILE_BYTES)   // 20480 (A tile + B tile)
#define SMEM_TOTAL (NSTAGE * STAGE_BYTES)
#define ITERS (3 * (K_TOTAL / BK))     // 3 split passes x 64 k-chunks = 192

// ---------------- scratch (__device__ globals: allocation-free) ----------------
__device__ __align__(128) float g_xsq[M_TOTAL];
__device__ __align__(128) float g_wsq[N_TOTAL];
__device__ __align__(128) __nv_bfloat16 g_xhi[(size_t)M_TOTAL * K_TOTAL];
__device__ __align__(128) __nv_bfloat16 g_xlo[(size_t)M_TOTAL * K_TOTAL];
__device__ __align__(128) __nv_bfloat16 g_whi[(size_t)N_TOTAL * K_TOTAL];  // [N,K] (transposed)
__device__ __align__(128) __nv_bfloat16 g_wlo[(size_t)N_TOTAL * K_TOTAL];

__device__ __forceinline__ uint32_t smem_u32(const void* p) {
    uint32_t a;
    asm("{ .reg .u64 t; cvta.to.shared.u64 t, %1; cvt.u32.u64 %0, t; }" : "=r"(a) : "l"(p));
    return a;
}
__device__ __forceinline__ uint32_t pack_bf2(__nv_bfloat16 a, __nv_bfloat16 b) {
    __nv_bfloat162 p(a, b);
    return *reinterpret_cast<uint32_t*>(&p);
}

// ---------------- prep: split-convert x + row sumsq (one pass over x) ----------------
__global__ void conv_x_kernel(const float* __restrict__ x) {
    const int row = blockIdx.x;
    const size_t base = (size_t)row * K_TOTAL + threadIdx.x * 8;
    float4 v0 = *reinterpret_cast<const float4*>(x + base);
    float4 v1 = *reinterpret_cast<const float4*>(x + base + 4);
    float v[8] = {v0.x, v0.y, v0.z, v0.w, v1.x, v1.y, v1.z, v1.w};
    __nv_bfloat16 h[8], l[8];
    float sum = 0.f;
#pragma unroll
    for (int i = 0; i < 8; i++) {
        h[i] = __float2bfloat16(v[i]);
        l[i] = __float2bfloat16(v[i] - __bfloat162float(h[i]));
        sum += v[i] * v[i];
    }
    uint4 hp = make_uint4(pack_bf2(h[0], h[1]), pack_bf2(h[2], h[3]), pack_bf2(h[4], h[5]), pack_bf2(h[6], h[7]));
    uint4 lp = make_uint4(pack_bf2(l[0], l[1]), pack_bf2(l[2], l[3]), pack_bf2(l[4], l[5]), pack_bf2(l[6], l[7]));
    *reinterpret_cast<uint4*>(&g_xhi[base]) = hp;
    *reinterpret_cast<uint4*>(&g_xlo[base]) = lp;
#pragma unroll
    for (int off = 16; off > 0; off >>= 1) sum += __shfl_xor_sync(0xffffffffu, sum, off);
    __shared__ float s[8];
    if ((threadIdx.x & 31) == 0) s[threadIdx.x >> 5] = sum;
    __syncthreads();
    if (threadIdx.x < 8) {
        float t = s[threadIdx.x];
#pragma unroll
        for (int off = 4; off > 0; off >>= 1) t += __shfl_xor_sync(0xffu, t, off);
        if (threadIdx.x == 0) g_xsq[row] = t;
    }
}

__global__ void zero_wsq_kernel() {
    int i = blockIdx.x * blockDim.x + threadIdx.x;
    if (i < N_TOTAL) g_wsq[i] = 0.f;
}

// ---------------- prep: transpose + split-convert W + col sumsq ----------------
__global__ void conv_w_kernel(const float* __restrict__ w) {
    __shared__ float t[32][33];
    const int k0 = blockIdx.y * 32, n0 = blockIdx.x * 32;
    const int tx = threadIdx.x & 31, ty = threadIdx.x >> 5;  // 32 x 8
#pragma unroll
    for (int j = 0; j < 32; j += 8)
        t[ty + j][tx] = w[(size_t)(k0 + ty + j) * N_TOTAL + n0 + tx];
    __syncthreads();
#pragma unroll
    for (int j = 0; j < 32; j += 8) {
        float v = t[tx][ty + j];  // (k = k0+tx, n = n0+ty+j)
        __nv_bfloat16 h = __float2bfloat16(v);
        __nv_bfloat16 l = __float2bfloat16(v - __bfloat162float(h));
        size_t o = (size_t)(n0 + ty + j) * K_TOTAL + k0 + tx;
        g_whi[o] = h;
        g_wlo[o] = l;
        float sq = v * v;
#pragma unroll
        for (int off = 16; off > 0; off >>= 1) sq += __shfl_xor_sync(0xffffffffu, sq, off);
        if (tx == 0) atomicAdd(&g_wsq[n0 + ty + j], sq);
    }
}

// ---------------- main: mma.sync bf16 GEMM (3-pass split) + Yat epilogue ----------------
#define MMA_BF16(acc, a, b)                                                         \
    asm volatile(                                                                   \
        "mma.sync.aligned.m16n8k16.row.col.f32.bf16.bf16.f32 "                      \
        "{%0,%1,%2,%3}, {%4,%5,%6,%7}, {%8,%9}, {%0,%1,%2,%3};"                     \
        : "+f"(acc[0]), "+f"(acc[1]), "+f"(acc[2]), "+f"(acc[3])                    \
        : "r"(a[0]), "r"(a[1]), "r"(a[2]), "r"(a[3]), "r"(b[0]), "r"(b[1]))

__global__ void __launch_bounds__(256, 2)
yat_mma_kernel(const float* __restrict__ bias, const float* __restrict__ alpha,
               float* __restrict__ C) {
    extern __shared__ __align__(128) char smem[];
    const uint32_t sb = smem_u32(smem);
    const int tid = threadIdx.x;
    const int wid = tid >> 5, lid = tid & 31;
    const int g = lid >> 2, t4 = lid & 3;
    const int wm = wid >> 2, wn = wid & 3;          // 2x4 warp grid
    const int row0 = blockIdx.y * BM;
    const int col0 = blockIdx.x * BN;

    float acc[4][4][4];
#pragma unroll
    for (int i = 0; i < 4; i++)
#pragma unroll
        for (int j = 0; j < 4; j++)
#pragma unroll
            for (int r = 0; r < 4; r++) acc[i][j][r] = 0.f;

    // per-thread cp.async mapping: 2 x 16B for A, 2 x 16B for B
    auto issue = [&](int it, int s) {
        const int p = it >> 6, kt = it & 63;
        const __nv_bfloat16* gA = (p == 2) ? g_xlo : g_xhi;
        const __nv_bfloat16* gB = (p == 1) ? g_wlo : g_whi;
        const uint32_t stb = sb + s * STAGE_BYTES;
#pragma unroll
        for (int i = 0; i < 2; i++) {
            const int idx = tid + i * 256;
            const int r = idx >> 2, c = idx & 3;
            const void* ga = gA + (size_t)(row0 + r) * K_TOTAL + kt * BK + c * 8;
            const uint32_t sa = stb + r * SROW + c * 16;
            asm volatile("cp.async.cg.shared.global [%0], [%1], 16;" :: "r"(sa), "l"(ga) : "memory");
            const void* gb = gB + (size_t)(col0 + r) * K_TOTAL + kt * BK + c * 8;
            const uint32_t sbb = stb + TILE_BYTES + r * SROW + c * 16;
            asm volatile("cp.async.cg.shared.global [%0], [%1], 16;" :: "r"(sbb), "l"(gb) : "memory");
        }
        asm volatile("cp.async.commit_group;" ::: "memory");
    };

#pragma unroll
    for (int s = 0; s < NSTAGE - 1; s++) issue(s, s);

    for (int it = 0; it < ITERS; ++it) {
        asm volatile("cp.async.wait_group %0;" :: "n"(NSTAGE - 2) : "memory");
        __syncthreads();
        if (it + NSTAGE - 1 < ITERS) issue(it + NSTAGE - 1, (it + NSTAGE - 1) & (NSTAGE - 1));

        const uint32_t Asb = sb + (it & (NSTAGE - 1)) * STAGE_BYTES;
        const uint32_t Bsb = Asb + TILE_BYTES;
#pragma unroll
        for (int kk = 0; kk < 2; kk++) {
            uint32_t a[4][4], b[4][2];
#pragma unroll
            for (int tm = 0; tm < 4; tm++) {
                const uint32_t ad = Asb + (wm * 64 + tm * 16 + g) * SROW + kk * 32 + 4 * t4;
                asm volatile("ld.shared.b32 %0, [%1];" : "=r"(a[tm][0]) : "r"(ad));
                asm volatile("ld.shared.b32 %0, [%1];" : "=r"(a[tm][1]) : "r"(ad + 8 * SROW));
                asm volatile("ld.shared.b32 %0, [%1];" : "=r"(a[tm][2]) : "r"(ad + 16));
                asm volatile("ld.shared.b32 %0, [%1];" : "=r"(a[tm][3]) : "r"(ad + 8 * SROW + 16));
            }
#pragma unroll
            for (int tn = 0; tn < 4; tn++) {
                const uint32_t bd = Bsb + (wn * 32 + tn * 8 + g) * SROW + kk * 32 + 4 * t4;
                asm volatile("ld.shared.b32 %0, [%1];" : "=r"(b[tn][0]) : "r"(bd));
                asm volatile("ld.shared.b32 %0, [%1];" : "=r"(b[tn][1]) : "r"(bd + 16));
            }
#pragma unroll
            for (int tm = 0; tm < 4; tm++)
#pragma unroll
                for (int tn = 0; tn < 4; tn++) MMA_BF16(acc[tm][tn], a[tm], b[tn]);
        }
    }

    // -------------------- fused Yat epilogue --------------------
    const float a_exp = __ldg(alpha);
    const float scale = powf(sqrtf(2048.0f) / logf(2049.0f), a_exp);
#pragma unroll
    for (int tm = 0; tm < 4; tm++) {
        const int ra = row0 + wm * 64 + tm * 16 + g;
        const float xs0 = g_xsq[ra];
        const float xs1 = g_xsq[ra + 8];
#pragma unroll
        for (int tn = 0; tn < 4; tn++) {
            const int c = col0 + wn * 32 + tn * 8 + 2 * t4;
            const float w0 = g_wsq[c], w1 = g_wsq[c + 1];
            const float b0 = bias[c], b1 = bias[c + 1];
            float y;
            float2 o;
            y = acc[tm][tn][0];
            o.x = (y * y / (xs0 + w0 - 2.f * y + EPS) + b0) * scale;
            y = acc[tm][tn][1];
            o.y = (y * y / (xs0 + w1 - 2.f * y + EPS) + b1) * scale;
            *reinterpret_cast<float2*>(C + (size_t)ra * N_TOTAL + c) = o;
            y = acc[tm][tn][2];
            o.x = (y * y / (xs1 + w0 - 2.f * y + EPS) + b0) * scale;
            y = acc[tm][tn][3];
            o.y = (y * y / (xs1 + w1 - 2.f * y + EPS) + b1) * scale;
            *reinterpret_cast<float2*>(C + (size_t)(ra + 8) * N_TOTAL + c) = o;
        }
    }
}

// ---------------- launch ----------------
extern "C" void kernel_launch(void* const* d_in, const int* in_sizes, int n_in,
                              void* d_out, int out_size) {
    const float* x     = (const float*)d_in[0];
    const float* w     = (const float*)d_in[1];
    const float* bias  = (const float*)d_in[2];
    const float* alpha = (const float*)d_in[3];
    float* out = (float*)d_out;

    cudaFuncSetAttribute(yat_mma_kernel, cudaFuncAttributeMaxDynamicSharedMemorySize, SMEM_TOTAL);

    zero_wsq_kernel<<<(N_TOTAL + 255) / 256, 256>>>();
    conv_x_kernel<<<M_TOTAL, 256>>>(x);
    conv_w_kernel<<<dim3(N_TOTAL / 32, K_TOTAL / 32), 256>>>(w);
    yat_mma_kernel<<<dim3(N_TOTAL / BN, M_TOTAL / BM), 256, SMEM_TOTAL>>>(bias, alpha, out);
}